// round 8
// baseline (speedup 1.0000x reference)
#include <cuda_runtime.h>
#include <math.h>

// Problem constants
#define B_    2
#define QS_   2048
#define MS_   2048
#define KS_   4096      // MS + QS
#define H_    1024
#define NH_   16
#define HD_   64
#define SCALE_ 0.125f   // 1/sqrt(64)
#define LN_EPS_ 1e-5f

// ---------------------------------------------------------------------------
// Scratch (device globals — no runtime allocation allowed)
// ---------------------------------------------------------------------------
__device__ float g_kv  [(size_t)B_ * KS_ * 2 * NH_ * HD_]; // KV projection    [8192,2048]
__device__ float g_q   [(size_t)B_ * QS_ * NH_ * HD_];     // Q projection     [4096,1024]
__device__ float g_att [(size_t)B_ * QS_ * NH_ * HD_];     // attention output [4096,1024]
__device__ float g_proj[(size_t)B_ * QS_ * H_];            // x + att@W_o      [4096,1024]

// ---------------------------------------------------------------------------
// fp32 -> tf32 round-to-nearest; m16n8k8 tf32 mma
// ---------------------------------------------------------------------------
__device__ __forceinline__ unsigned f2tf(float f) {
    unsigned u;
    asm("cvt.rna.tf32.f32 %0, %1;" : "=r"(u) : "f"(f));
    return u;
}

__device__ __forceinline__ uint4 f2tf4(float4 v) {
    uint4 r;
    r.x = f2tf(v.x); r.y = f2tf(v.y); r.z = f2tf(v.z); r.w = f2tf(v.w);
    return r;
}

__device__ __forceinline__ void mma_tf32(float c[4],
                                         unsigned a0, unsigned a1, unsigned a2, unsigned a3,
                                         unsigned b0, unsigned b1) {
    asm("mma.sync.aligned.m16n8k8.row.col.f32.tf32.tf32.f32 "
        "{%0,%1,%2,%3}, {%4,%5,%6,%7}, {%8,%9}, {%0,%1,%2,%3};"
        : "+f"(c[0]), "+f"(c[1]), "+f"(c[2]), "+f"(c[3])
        : "r"(a0), "r"(a1), "r"(a2), "r"(a3), "r"(b0), "r"(b1));
}

// ---------------------------------------------------------------------------
// tf32 tensor-core GEMM: C[M,N] = A[M,K] @ B[K,N] (+ resid), row-major fp32.
// Block tile 128x128, K-chunk 32. 256 threads = 8 warps (2x4), each warp
// computes 64x32 via 4x4 fragments of mma.m16n8k8.
// DOUBLE-BUFFERED smem (ping-pong): ONE __syncthreads per chunk.
// CONCAT=1 fuses concat(mem, x) into the A-row pointer resolution.
// RESID=1 adds resid[row, col] in the epilogue (residual fusion).
// Requires M%128==0, N%128==0, K%32==0.
// Smem pads for conflict-free fragment LOADS:
//   As pad 36 (stride%32==4): A-frag bank = 4g + t4  -> bijective over warp
//   Bs pad 136 (stride%32==8): B-frag bank = 8*t4+g  -> bijective over warp
// Stage size = 128*36 + 32*136 = 8960 words; 2 stages = 71680 B dynamic smem.
// ---------------------------------------------------------------------------
#define GEMM_STAGE_WORDS (128 * 36 + 32 * 136)
#define GEMM_SMEM_BYTES  (2 * GEMM_STAGE_WORDS * 4)

template <int CONCAT, int RESID>
__global__ __launch_bounds__(256) void gemm_tf32(const float* __restrict__ Ax,
                                                 const float* __restrict__ mem,
                                                 const float* __restrict__ Bm,
                                                 const float* __restrict__ resid,
                                                 float* __restrict__ C,
                                                 int M, int N, int K) {
    extern __shared__ __align__(16) unsigned gsm[];
    // stage s: A at gsm + s*STAGE (row stride 36), B at +128*36 (row stride 136)

    int tid  = threadIdx.x;
    int lane = tid & 31;
    int wid  = tid >> 5;
    int wm   = wid >> 2;          // 0..1
    int wn   = wid & 3;           // 0..3
    int g    = lane >> 2;         // groupID 0..7
    int t4   = lane & 3;          // 0..3

    int bm = blockIdx.y * 128;
    int bn = blockIdx.x * 128;

    const float* arowp[4];
    int ar[4], ac4[4];
#pragma unroll
    for (int j = 0; j < 4; j++) {
        int idx = tid + 256 * j;       // 128 rows x 8 float4-cols
        ar[j]  = idx >> 3;
        ac4[j] = idx & 7;
        if (CONCAT) {
            int grow = bm + ar[j];
            int b = grow / KS_;
            int s = grow % KS_;
            arowp[j] = (s < MS_)
                ? mem + ((size_t)b * MS_ + s) * H_ + ac4[j] * 4
                : Ax  + ((size_t)b * QS_ + (s - MS_)) * H_ + ac4[j] * 4;
        } else {
            arowp[j] = Ax + (size_t)(bm + ar[j]) * K + ac4[j] * 4;
        }
    }
    const float* browp[4];
    int br[4], bc4[4];
#pragma unroll
    for (int j = 0; j < 4; j++) {
        int idx = tid + 256 * j;       // 32 rows x 32 float4-cols
        br[j]  = idx >> 5;
        bc4[j] = idx & 31;
        browp[j] = Bm + (size_t)br[j] * N + bn + bc4[j] * 4;
    }

    float acc[4][4][4];
#pragma unroll
    for (int i = 0; i < 4; i++)
#pragma unroll
        for (int j = 0; j < 4; j++)
#pragma unroll
            for (int v = 0; v < 4; v++) acc[i][j][v] = 0.f;

    // ---- Fill stage 0 with chunk 0 ----
    {
        unsigned* As0 = gsm;
        unsigned* Bs0 = gsm + 128 * 36;
#pragma unroll
        for (int j = 0; j < 4; j++) {
            float4 pa = *(const float4*)(arowp[j]);
            float4 pb = *(const float4*)(browp[j]);
            *(uint4*)&As0[ar[j] * 36 + ac4[j] * 4] = f2tf4(pa);
            *(uint4*)&Bs0[br[j] * 136 + bc4[j] * 4] = f2tf4(pb);
        }
    }
    __syncthreads();

    int nchunks = K / 32;
    for (int c = 0; c < nchunks; c++) {
        unsigned* Acur = gsm + (c & 1) * GEMM_STAGE_WORDS;
        unsigned* Bcur = Acur + 128 * 36;
        unsigned* Anxt = gsm + ((c + 1) & 1) * GEMM_STAGE_WORDS;
        unsigned* Bnxt = Anxt + 128 * 36;

        // Issue next chunk's global loads (consumed after the compute phase)
        float4 pa[4], pb[4];
        bool hasnext = (c + 1 < nchunks);
        if (hasnext) {
            int k0 = (c + 1) * 32;
#pragma unroll
            for (int j = 0; j < 4; j++) {
                pa[j] = *(const float4*)(arowp[j] + k0);
                pb[j] = *(const float4*)(browp[j] + (size_t)k0 * N);
            }
        }

        // Compute on current stage
#pragma unroll
        for (int ks = 0; ks < 32; ks += 8) {
            unsigned bf[4][2];
#pragma unroll
            for (int fn = 0; fn < 4; fn++) {
                int cb = wn * 32 + fn * 8 + g;
                bf[fn][0] = Bcur[(ks + t4) * 136 + cb];
                bf[fn][1] = Bcur[(ks + t4 + 4) * 136 + cb];
            }
#pragma unroll
            for (int fm = 0; fm < 4; fm++) {
                int rb = wm * 64 + fm * 16;
                unsigned a0 = Acur[(rb + g) * 36 + ks + t4];
                unsigned a1 = Acur[(rb + g + 8) * 36 + ks + t4];
                unsigned a2 = Acur[(rb + g) * 36 + ks + t4 + 4];
                unsigned a3 = Acur[(rb + g + 8) * 36 + ks + t4 + 4];
#pragma unroll
                for (int fn = 0; fn < 4; fn++)
                    mma_tf32(acc[fm][fn], a0, a1, a2, a3, bf[fn][0], bf[fn][1]);
            }
        }

        // Store next chunk into the idle stage; single barrier per chunk
        if (hasnext) {
#pragma unroll
            for (int j = 0; j < 4; j++) {
                *(uint4*)&Anxt[ar[j] * 36 + ac4[j] * 4] = f2tf4(pa[j]);
                *(uint4*)&Bnxt[br[j] * 136 + bc4[j] * 4] = f2tf4(pb[j]);
            }
            __syncthreads();
        }
    }

#pragma unroll
    for (int fm = 0; fm < 4; fm++) {
#pragma unroll
        for (int fn = 0; fn < 4; fn++) {
            int row = bm + wm * 64 + fm * 16 + g;
            int col = bn + wn * 32 + fn * 8 + 2 * t4;
            float2 v0 = make_float2(acc[fm][fn][0], acc[fm][fn][1]);
            float2 v1 = make_float2(acc[fm][fn][2], acc[fm][fn][3]);
            if (RESID) {
                float2 r0 = *(const float2*)&resid[(size_t)row * N + col];
                float2 r1 = *(const float2*)&resid[(size_t)(row + 8) * N + col];
                v0.x += r0.x; v0.y += r0.y;
                v1.x += r1.x; v1.y += r1.y;
            }
            *(float2*)&C[(size_t)row * N + col]       = v0;
            *(float2*)&C[(size_t)(row + 8) * N + col] = v1;
        }
    }
}

// ---------------------------------------------------------------------------
// Tensor-core flash attention. One block = (128-query tile, head, batch),
// 256 threads = 8 warps; warp w owns query rows [16w, 16w+16).
// Q held in A-fragments in registers for the whole block. Per 64-key tile:
//   S = Q K^T via mma (K B-frags from smem), online softmax in fragment regs
//   (row stats via shfl over quad groups), P -> smem (tf32), O += P V via mma.
// K/V fill is statically unrolled with an explicit load-phase/store-phase
// split: all 8 LDG.128 issue back-to-back (MLP=8) before the first STS, so
// the L2-hit latency (~240cyc; g_kv fits in L2) is paid once, not per pair.
// Smem pads for conflict-free fragment loads:
//   Ks/Ps pad 68 (stride%32==4): bank = 4g + t4   bijective over warp
//   Vs    pad 72 (stride%32==8): bank = 8*t4 + g  bijective over warp
// Mask analytic: key k valid iff k <= q + MS. For a 128-row q-tile the
// boundary crosses the final TWO k-tiles (kt >= nkt-2); every row keeps at
// least one valid key in each of its partial tiles.
// ---------------------------------------------------------------------------
#define ATTN_SMEM_BYTES ((64 * 68 + 64 * 72 + 128 * 68) * 4)   // Ks+Vs+Ps = 70656

__global__ __launch_bounds__(256) void attn_kernel() {
    extern __shared__ __align__(16) unsigned smn[];
    unsigned (*Ks)[68] = (unsigned (*)[68])smn;                    // [64][68]
    unsigned (*Vs)[72] = (unsigned (*)[72])(smn + 64 * 68);        // [64][72]
    unsigned (*Ps)[68] = (unsigned (*)[68])(smn + 64 * (68 + 72)); // [128][68]

    int qt = blockIdx.x;   // 0..15  (128-row q-tiles)
    int h  = blockIdx.y;   // 0..15
    int b  = blockIdx.z;   // 0..1
    int tid  = threadIdx.x;
    int lane = tid & 31;
    int wid  = tid >> 5;        // 0..7
    int g    = lane >> 2;       // 0..7
    int t4   = lane & 3;        // 0..3
    int rb   = wid * 16;        // warp's row base within tile (0..112)

    // ---- Stage Q (scaled, tf32) into Ps: static unroll, batched loads ----
    {
        float4 qreg[8];
#pragma unroll
        for (int it = 0; it < 8; it++) {
            int i = tid + it * 256;            // 128 rows x 16 float4
            int r = i >> 4, c4 = i & 15;
            qreg[it] = *(const float4*)&g_q[((size_t)(b * QS_ + qt * 128 + r)) * (NH_ * HD_)
                                            + h * HD_ + c4 * 4];
        }
#pragma unroll
        for (int it = 0; it < 8; it++) {
            int i = tid + it * 256;
            int r = i >> 4, c4 = i & 15;
            float4 v = qreg[it];
            v.x *= SCALE_; v.y *= SCALE_; v.z *= SCALE_; v.w *= SCALE_;
            *(uint4*)&Ps[r][c4 * 4] = f2tf4(v);
        }
    }
    __syncthreads();

    unsigned qf[8][4];
#pragma unroll
    for (int ks = 0; ks < 8; ks++) {
        qf[ks][0] = Ps[rb + g][ks * 8 + t4];
        qf[ks][1] = Ps[rb + g + 8][ks * 8 + t4];
        qf[ks][2] = Ps[rb + g][ks * 8 + t4 + 4];
        qf[ks][3] = Ps[rb + g + 8][ks * 8 + t4 + 4];
    }
    __syncthreads();   // Ps reused as P buffer below

    float oacc[8][4];
#pragma unroll
    for (int fn = 0; fn < 8; fn++)
#pragma unroll
        for (int v = 0; v < 4; v++) oacc[fn][v] = 0.f;
    float m_lo = -INFINITY, m_hi = -INFINITY, l_lo = 0.f, l_hi = 0.f;

    // Tiles 0 .. 2qt+33 contain at least one valid key for this q-tile.
    int nkt = 2 * qt + 34;
    for (int kt = 0; kt < nkt; kt++) {
        // ---- Fill K and V tiles: batched loads (MLP=8), then stores ----
        {
            float4 kreg[4], vreg[4];
#pragma unroll
            for (int it = 0; it < 4; it++) {
                int i = tid + it * 256;        // 64 rows x 16 float4
                int r = i >> 4, c4 = i & 15;
                const float* kp = &g_kv[((size_t)(b * KS_ + kt * 64 + r)) * (2 * NH_ * HD_)
                                        + h * HD_ + c4 * 4];
                kreg[it] = *(const float4*)kp;
                vreg[it] = *(const float4*)(kp + NH_ * HD_);
            }
#pragma unroll
            for (int it = 0; it < 4; it++) {
                int i = tid + it * 256;
                int r = i >> 4, c4 = i & 15;
                *(uint4*)&Ks[r][c4 * 4] = f2tf4(kreg[it]);
                *(uint4*)&Vs[r][c4 * 4] = f2tf4(vreg[it]);
            }
        }
        __syncthreads();

        // ---- S = Q K^T  (B-frag: Beff[d][key] = K[key][d]) ----
        float sf[8][4];
#pragma unroll
        for (int fn = 0; fn < 8; fn++)
#pragma unroll
            for (int v = 0; v < 4; v++) sf[fn][v] = 0.f;
#pragma unroll
        for (int ks = 0; ks < 8; ks++) {
#pragma unroll
            for (int fn = 0; fn < 8; fn++) {
                unsigned b0 = Ks[fn * 8 + g][ks * 8 + t4];
                unsigned b1 = Ks[fn * 8 + g][ks * 8 + t4 + 4];
                mma_tf32(sf[fn], qf[ks][0], qf[ks][1], qf[ks][2], qf[ks][3], b0, b1);
            }
        }

        // ---- Mask (boundary crosses the final two k-tiles) ----
        if (kt >= nkt - 2) {
#pragma unroll
            for (int fn = 0; fn < 8; fn++) {
#pragma unroll
                for (int e = 0; e < 4; e++) {
                    int row = qt * 128 + rb + g + ((e >> 1) << 3);
                    int col = kt * 64 + fn * 8 + 2 * t4 + (e & 1);
                    if (col > row + MS_) sf[fn][e] = -1e30f;
                }
            }
        }

        // ---- Online softmax in fragment registers ----
        float tmax_lo = -INFINITY, tmax_hi = -INFINITY;
#pragma unroll
        for (int fn = 0; fn < 8; fn++) {
            tmax_lo = fmaxf(tmax_lo, fmaxf(sf[fn][0], sf[fn][1]));
            tmax_hi = fmaxf(tmax_hi, fmaxf(sf[fn][2], sf[fn][3]));
        }
        tmax_lo = fmaxf(tmax_lo, __shfl_xor_sync(0xffffffffu, tmax_lo, 1));
        tmax_lo = fmaxf(tmax_lo, __shfl_xor_sync(0xffffffffu, tmax_lo, 2));
        tmax_hi = fmaxf(tmax_hi, __shfl_xor_sync(0xffffffffu, tmax_hi, 1));
        tmax_hi = fmaxf(tmax_hi, __shfl_xor_sync(0xffffffffu, tmax_hi, 2));

        float mn_lo = fmaxf(m_lo, tmax_lo);
        float mn_hi = fmaxf(m_hi, tmax_hi);
        float al_lo = __expf(m_lo - mn_lo);   // first tile: exp(-inf) = 0
        float al_hi = __expf(m_hi - mn_hi);

        float sum_lo = 0.f, sum_hi = 0.f;
#pragma unroll
        for (int fn = 0; fn < 8; fn++) {
            float p0 = __expf(sf[fn][0] - mn_lo);
            float p1 = __expf(sf[fn][1] - mn_lo);
            float p2 = __expf(sf[fn][2] - mn_hi);
            float p3 = __expf(sf[fn][3] - mn_hi);
            sum_lo += p0 + p1;
            sum_hi += p2 + p3;
            *(uint2*)&Ps[rb + g][fn * 8 + 2 * t4]     = make_uint2(f2tf(p0), f2tf(p1));
            *(uint2*)&Ps[rb + g + 8][fn * 8 + 2 * t4] = make_uint2(f2tf(p2), f2tf(p3));
        }
        sum_lo += __shfl_xor_sync(0xffffffffu, sum_lo, 1);
        sum_lo += __shfl_xor_sync(0xffffffffu, sum_lo, 2);
        sum_hi += __shfl_xor_sync(0xffffffffu, sum_hi, 1);
        sum_hi += __shfl_xor_sync(0xffffffffu, sum_hi, 2);

        l_lo = l_lo * al_lo + sum_lo;
        l_hi = l_hi * al_hi + sum_hi;
        m_lo = mn_lo;
        m_hi = mn_hi;

#pragma unroll
        for (int fn = 0; fn < 8; fn++) {
            oacc[fn][0] *= al_lo;
            oacc[fn][1] *= al_lo;
            oacc[fn][2] *= al_hi;
            oacc[fn][3] *= al_hi;
        }
        __syncwarp();   // P written/read only within this warp's 16-row strip

        // ---- O += P V  (A-frag from Ps, B-frag: V[k][d]) ----
#pragma unroll
        for (int ks = 0; ks < 8; ks++) {
            unsigned a0 = Ps[rb + g][ks * 8 + t4];
            unsigned a1 = Ps[rb + g + 8][ks * 8 + t4];
            unsigned a2 = Ps[rb + g][ks * 8 + t4 + 4];
            unsigned a3 = Ps[rb + g + 8][ks * 8 + t4 + 4];
#pragma unroll
            for (int fn = 0; fn < 8; fn++) {
                unsigned b0 = Vs[ks * 8 + t4][fn * 8 + g];
                unsigned b1 = Vs[ks * 8 + t4 + 4][fn * 8 + g];
                mma_tf32(oacc[fn], a0, a1, a2, a3, b0, b1);
            }
        }
        __syncthreads();   // Ks/Vs overwritten next iteration
    }

    // ---- Epilogue: normalize and store ----
    float inv_lo = 1.f / l_lo;
    float inv_hi = 1.f / l_hi;
    int row_lo = b * QS_ + qt * 128 + rb + g;
#pragma unroll
    for (int fn = 0; fn < 8; fn++) {
        int col = h * HD_ + fn * 8 + 2 * t4;
        *(float2*)&g_att[(size_t)row_lo * (NH_ * HD_) + col] =
            make_float2(oacc[fn][0] * inv_lo, oacc[fn][1] * inv_lo);
        *(float2*)&g_att[(size_t)(row_lo + 8) * (NH_ * HD_) + col] =
            make_float2(oacc[fn][2] * inv_hi, oacc[fn][3] * inv_hi);
    }
}

// ---------------------------------------------------------------------------
// LayerNorm over g_proj (residual already fused into the O-proj epilogue):
// out = LN(g_proj) * gamma + beta.  One block per row (H=1024).
// ---------------------------------------------------------------------------
__global__ __launch_bounds__(256) void ln_kernel(const float* __restrict__ gamma,
                                                 const float* __restrict__ beta,
                                                 float* __restrict__ out) {
    int row = blockIdx.x;
    int tid = threadIdx.x;
    size_t base = (size_t)row * H_ + tid * 4;

    float4 pv = *(const float4*)&g_proj[base];
    float y0 = pv.x, y1 = pv.y, y2 = pv.z, y3 = pv.w;

    float sum = y0 + y1 + y2 + y3;
    float sq  = y0 * y0 + y1 * y1 + y2 * y2 + y3 * y3;

    __shared__ float ssum[8], ssq[8];
#pragma unroll
    for (int o = 16; o > 0; o >>= 1) {
        sum += __shfl_xor_sync(0xffffffffu, sum, o);
        sq  += __shfl_xor_sync(0xffffffffu, sq,  o);
    }
    if ((tid & 31) == 0) { ssum[tid >> 5] = sum; ssq[tid >> 5] = sq; }
    __syncthreads();
    float ts = 0.f, tq = 0.f;
#pragma unroll
    for (int i = 0; i < 8; i++) { ts += ssum[i]; tq += ssq[i]; }

    float mu  = ts * (1.f / H_);
    float var = tq * (1.f / H_) - mu * mu;
    float inv = rsqrtf(var + LN_EPS_);

    float4 gv = *(const float4*)&gamma[tid * 4];
    float4 bv = *(const float4*)&beta[tid * 4];
    float4 o;
    o.x = (y0 - mu) * inv * gv.x + bv.x;
    o.y = (y1 - mu) * inv * gv.y + bv.y;
    o.z = (y2 - mu) * inv * gv.z + bv.z;
    o.w = (y3 - mu) * inv * gv.w + bv.w;
    *(float4*)&out[base] = o;
}

// ---------------------------------------------------------------------------
// Launcher (graph-capturable: kernel launches + non-stream attribute/query APIs)
// ---------------------------------------------------------------------------
extern "C" void kernel_launch(void* const* d_in, const int* in_sizes, int n_in,
                              void* d_out, int out_size) {
    (void)in_sizes; (void)n_in; (void)out_size;
    const float* x    = (const float*)d_in[0];
    const float* mem  = (const float*)d_in[1];
    // d_in[2] = mask — analytic (k > q + MS), computed in-kernel, not read.
    const float* W_kv = (const float*)d_in[3];
    const float* W_q  = (const float*)d_in[4];
    const float* W_o  = (const float*)d_in[5];
    const float* ln_g = (const float*)d_in[6];
    const float* ln_b = (const float*)d_in[7];
    float* out = (float*)d_out;

    cudaFuncSetAttribute(attn_kernel, cudaFuncAttributeMaxDynamicSharedMemorySize,
                         ATTN_SMEM_BYTES);
    cudaFuncSetAttribute(gemm_tf32<0, 0>, cudaFuncAttributeMaxDynamicSharedMemorySize,
                         GEMM_SMEM_BYTES);
    cudaFuncSetAttribute(gemm_tf32<1, 0>, cudaFuncAttributeMaxDynamicSharedMemorySize,
                         GEMM_SMEM_BYTES);
    cudaFuncSetAttribute(gemm_tf32<0, 1>, cudaFuncAttributeMaxDynamicSharedMemorySize,
                         GEMM_SMEM_BYTES);

    void *pkv, *pq, *patt, *pproj;
    cudaGetSymbolAddress(&pkv,   g_kv);
    cudaGetSymbolAddress(&pq,    g_q);
    cudaGetSymbolAddress(&patt,  g_att);
    cudaGetSymbolAddress(&pproj, g_proj);

    // 1. KV projection with fused concat: g_kv = concat(mem,x) @ W_kv
    gemm_tf32<1, 0><<<dim3(2048 / 128, (B_ * KS_) / 128), 256, GEMM_SMEM_BYTES>>>(
        x, mem, W_kv, nullptr, (float*)pkv, B_ * KS_, 2 * NH_ * HD_, H_);

    // 2. Q projection: g_q = x @ W_q
    gemm_tf32<0, 0><<<dim3(1024 / 128, (B_ * QS_) / 128), 256, GEMM_SMEM_BYTES>>>(
        x, nullptr, W_q, nullptr, (float*)pq, B_ * QS_, NH_ * HD_, H_);

    // 3. Tensor-core flash attention (128-query tiles)
    attn_kernel<<<dim3(QS_ / 128, NH_, B_), 256, ATTN_SMEM_BYTES>>>();

    // 4. Output projection + residual: g_proj = x + g_att @ W_o
    gemm_tf32<0, 1><<<dim3(1024 / 128, (B_ * QS_) / 128), 256, GEMM_SMEM_BYTES>>>(
        (const float*)patt, nullptr, W_o, x, (float*)pproj, B_ * QS_, H_, NH_ * HD_);

    // 5. LayerNorm -> d_out
    ln_kernel<<<B_ * QS_, 256>>>(ln_g, ln_b, out);
}

// round 15
// speedup vs baseline: 1.2187x; 1.2187x over previous
#include <cuda_runtime.h>
#include <math.h>

// Problem constants
#define B_    2
#define QS_   2048
#define MS_   2048
#define KS_   4096      // MS + QS
#define H_    1024
#define NH_   16
#define HD_   64
#define SCALE_ 0.125f   // 1/sqrt(64)
#define LOG2E_ 1.4426950408889634f
#define QSCALE_ (SCALE_ * LOG2E_)   // softmax done in exp2 domain
#define LN_EPS_ 1e-5f

// ---------------------------------------------------------------------------
// Scratch (device globals — no runtime allocation allowed)
// ---------------------------------------------------------------------------
__device__ float g_kv  [(size_t)B_ * KS_ * 2 * NH_ * HD_]; // KV projection    [8192,2048]
__device__ float g_q   [(size_t)B_ * QS_ * NH_ * HD_];     // Q projection     [4096,1024]
__device__ float g_att [(size_t)B_ * QS_ * NH_ * HD_];     // attention output [4096,1024]
__device__ float g_proj[(size_t)B_ * QS_ * H_];            // x + att@W_o      [4096,1024]

// ---------------------------------------------------------------------------
// Helpers. mma.tf32 truncates raw fp32 operand bits to tf32 in HW; measured
// rel_err with rna-rounding was 5.4e-6, so truncation (<= ~2x) is far inside
// the 1e-3 budget. This enables cp.async (pure byte copies).
// ---------------------------------------------------------------------------
__device__ __forceinline__ uint4 f4_as_u4(float4 v) {
    uint4 r;
    r.x = __float_as_uint(v.x); r.y = __float_as_uint(v.y);
    r.z = __float_as_uint(v.z); r.w = __float_as_uint(v.w);
    return r;
}

// Raw MUFU.EX2 (what __expf uses after its log2e FMUL — we pre-fold log2e
// into the Q scale instead, saving one FMUL per exponential).
__device__ __forceinline__ float fexp2(float x) {
    float r;
    asm("ex2.approx.ftz.f32 %0, %1;" : "=f"(r) : "f"(x));
    return r;
}

__device__ __forceinline__ void mma_tf32(float c[4],
                                         unsigned a0, unsigned a1, unsigned a2, unsigned a3,
                                         unsigned b0, unsigned b1) {
    asm("mma.sync.aligned.m16n8k8.row.col.f32.tf32.tf32.f32 "
        "{%0,%1,%2,%3}, {%4,%5,%6,%7}, {%8,%9}, {%0,%1,%2,%3};"
        : "+f"(c[0]), "+f"(c[1]), "+f"(c[2]), "+f"(c[3])
        : "r"(a0), "r"(a1), "r"(a2), "r"(a3), "r"(b0), "r"(b1));
}

// L2-only staging copy (.cg, 16B): staged tiles are consumed once from smem,
// so L1 allocation (.ca) is pure pollution — the round-8 profile showed L1 at
// 46.8% busy (top memory pipe). .cg keeps the L1/LSU path free for the
// fragment LDS traffic.
__device__ __forceinline__ void cp_async16(unsigned dst, const void* src) {
    asm volatile("cp.async.cg.shared.global [%0], [%1], 16;" :: "r"(dst), "l"(src));
}
__device__ __forceinline__ void cp_commit() {
    asm volatile("cp.async.commit_group;" ::: "memory");
}
__device__ __forceinline__ void cp_wait0() {
    asm volatile("cp.async.wait_group 0;" ::: "memory");
}

// ---------------------------------------------------------------------------
// tf32 tensor-core GEMM: C[M,N] = A[M,K] @ B[K,N] (+ resid), row-major fp32.
// Block tile 128x128, K-chunk 32. 256 threads = 8 warps (2x4), each warp
// 64x32 via 4x4 fragments of mma.m16n8k8.
// cp.async double-buffer (bypasses the register file — fixes the measured
// regs=174 / occ=12.3%); __launch_bounds__(256,2) -> 2 CTAs/SM = 16 warps.
// ONE __syncthreads per chunk:
//   wait_group 0; sync; issue copy(c+1) -> idle stage; compute(c).
//   compute(c) precedes the NEXT iteration's sync, so the copy into stage
//   c&1 (chunk c+2) cannot overtake compute(c).
// CONCAT=1 fuses concat(mem, x); RESID=1 adds resid in the epilogue.
// Smem pads for conflict-free fragment LOADS:
//   As pad 36 (stride%32==4): A-frag bank = 4g + t4  -> bijective over warp
//   Bs pad 136 (stride%32==8): B-frag bank = 8*t4+g  -> bijective over warp
// Stage = 128*36 + 32*136 = 8960 words; 2 stages = 71680 B dynamic smem.
// ---------------------------------------------------------------------------
#define GEMM_STAGE_WORDS (128 * 36 + 32 * 136)
#define GEMM_SMEM_BYTES  (2 * GEMM_STAGE_WORDS * 4)

template <int CONCAT, int RESID>
__global__ __launch_bounds__(256, 2) void gemm_tf32(const float* __restrict__ Ax,
                                                    const float* __restrict__ mem,
                                                    const float* __restrict__ Bm,
                                                    const float* __restrict__ resid,
                                                    float* __restrict__ C,
                                                    int M, int N, int K) {
    extern __shared__ __align__(16) unsigned gsm[];

    int tid  = threadIdx.x;
    int lane = tid & 31;
    int wid  = tid >> 5;
    int wm   = wid >> 2;          // 0..1
    int wn   = wid & 3;           // 0..3
    int g    = lane >> 2;         // groupID 0..7
    int t4   = lane & 3;          // 0..3

    int bm = blockIdx.y * 128;
    int bn = blockIdx.x * 128;

    const float* arowp[4];
    unsigned adst[4];
#pragma unroll
    for (int j = 0; j < 4; j++) {
        int idx = tid + 256 * j;       // 128 rows x 8 float4-cols
        int ar  = idx >> 3;
        int ac4 = idx & 7;
        adst[j] = (unsigned)(ar * 36 + ac4 * 4) * 4u;
        if (CONCAT) {
            int grow = bm + ar;
            int b = grow / KS_;
            int s = grow % KS_;
            arowp[j] = (s < MS_)
                ? mem + ((size_t)b * MS_ + s) * H_ + ac4 * 4
                : Ax  + ((size_t)b * QS_ + (s - MS_)) * H_ + ac4 * 4;
        } else {
            arowp[j] = Ax + (size_t)(bm + ar) * K + ac4 * 4;
        }
    }
    const float* browp[4];
    unsigned bdst[4];
#pragma unroll
    for (int j = 0; j < 4; j++) {
        int idx = tid + 256 * j;       // 32 rows x 32 float4-cols
        int br  = idx >> 5;
        int bc4 = idx & 31;
        bdst[j] = (unsigned)(br * 136 + bc4 * 4) * 4u;
        browp[j] = Bm + (size_t)br * N + bn + bc4 * 4;
    }

    unsigned sbase = (unsigned)__cvta_generic_to_shared(gsm);

    float acc[4][4][4];
#pragma unroll
    for (int i = 0; i < 4; i++)
#pragma unroll
        for (int j = 0; j < 4; j++)
#pragma unroll
            for (int v = 0; v < 4; v++) acc[i][j][v] = 0.f;

    // Prologue: async-copy chunk 0 into stage 0
    {
        unsigned aoff = sbase;
        unsigned boff = sbase + 128 * 36 * 4;
#pragma unroll
        for (int j = 0; j < 4; j++) cp_async16(aoff + adst[j], arowp[j]);
#pragma unroll
        for (int j = 0; j < 4; j++) cp_async16(boff + bdst[j], browp[j]);
        cp_commit();
    }

    int nchunks = K / 32;
    for (int c = 0; c < nchunks; c++) {
        cp_wait0();
        __syncthreads();

        if (c + 1 < nchunks) {
            int k0 = (c + 1) * 32;
            unsigned aoff = sbase + (unsigned)((c + 1) & 1) * (GEMM_STAGE_WORDS * 4);
            unsigned boff = aoff + 128 * 36 * 4;
#pragma unroll
            for (int j = 0; j < 4; j++) cp_async16(aoff + adst[j], arowp[j] + k0);
#pragma unroll
            for (int j = 0; j < 4; j++) cp_async16(boff + bdst[j], browp[j] + (size_t)k0 * N);
            cp_commit();
        }

        const unsigned* Acur = gsm + (c & 1) * GEMM_STAGE_WORDS;
        const unsigned* Bcur = Acur + 128 * 36;
#pragma unroll
        for (int ks = 0; ks < 32; ks += 8) {
            unsigned bf[4][2];
#pragma unroll
            for (int fn = 0; fn < 4; fn++) {
                int cb = wn * 32 + fn * 8 + g;
                bf[fn][0] = Bcur[(ks + t4) * 136 + cb];
                bf[fn][1] = Bcur[(ks + t4 + 4) * 136 + cb];
            }
#pragma unroll
            for (int fm = 0; fm < 4; fm++) {
                int rb = wm * 64 + fm * 16;
                unsigned a0 = Acur[(rb + g) * 36 + ks + t4];
                unsigned a1 = Acur[(rb + g + 8) * 36 + ks + t4];
                unsigned a2 = Acur[(rb + g) * 36 + ks + t4 + 4];
                unsigned a3 = Acur[(rb + g + 8) * 36 + ks + t4 + 4];
#pragma unroll
                for (int fn = 0; fn < 4; fn++)
                    mma_tf32(acc[fm][fn], a0, a1, a2, a3, bf[fn][0], bf[fn][1]);
            }
        }
    }

#pragma unroll
    for (int fm = 0; fm < 4; fm++) {
#pragma unroll
        for (int fn = 0; fn < 4; fn++) {
            int row = bm + wm * 64 + fm * 16 + g;
            int col = bn + wn * 32 + fn * 8 + 2 * t4;
            float2 v0 = make_float2(acc[fm][fn][0], acc[fm][fn][1]);
            float2 v1 = make_float2(acc[fm][fn][2], acc[fm][fn][3]);
            if (RESID) {
                float2 r0 = *(const float2*)&resid[(size_t)row * N + col];
                float2 r1 = *(const float2*)&resid[(size_t)(row + 8) * N + col];
                v0.x += r0.x; v0.y += r0.y;
                v1.x += r1.x; v1.y += r1.y;
            }
            *(float2*)&C[(size_t)row * N + col]       = v0;
            *(float2*)&C[(size_t)(row + 8) * N + col] = v1;
        }
    }
}

// ---------------------------------------------------------------------------
// Tensor-core flash attention with cp.async DOUBLE-BUFFERED K/V tiles.
// One block = (128-query tile, head, batch), 256 threads = 8 warps; warp w
// owns query rows [16w, 16w+16). Q in register A-frags for the whole block,
// pre-scaled by SCALE*log2(e): the whole online softmax runs in the exp2
// domain (p = 2^(s'-m'), alpha = 2^(m'old-m'new)) via raw MUFU.EX2 — one
// FMUL per exponential removed vs __expf, algebraically identical.
// HEAVY-FIRST SCHEDULING: work per CTA is nkt = 2*qt+34 (34..63, 1.85x
// spread); grid 512 CTAs on ~296 slots = 2 waves. qt = 15 - blockIdx.x puts
// heavy q-tiles in wave 1 so light ones pack into the stragglers' shadow.
// Per 64-key tile:
//   wait_group 0; syncthreads; issue cp.async for tile kt+1 into idle buf;
//   S = Q K^T (mma), mask, online softmax (frag regs, quad-group shfl),
//   P -> Ps (warp-private, __syncwarp), O += P V (mma).
// Race safety: compute(kt) reads buf kt&1; the next copy into that buffer is
// issued at iteration kt+1 AFTER its top __syncthreads, which fences
// compute(kt) on all threads (same argument as the GEMM).
// __launch_bounds__(256,2): live set ~116 regs -> 2 CTAs/SM;
// smem 2 x 104KB = 208KB <= 228KB/SM.
// smem layout (words): buf0 Ks@0 Vs@4352 | buf1 Ks@8960 Vs@13312 | Ps@17920.
// All bases = 0 mod 32 words -> conflict-free bank maps preserved:
//   Ks/Ps pad 68 (stride%32==4): bank = 4g + t4   bijective over warp
//   Vs    pad 72 (stride%32==8): bank = 8*t4 + g  bijective over warp
// Mask analytic: key k valid iff k <= q + MS; boundary crosses the final TWO
// k-tiles (kt >= nkt-2); every row keeps >= 1 valid key in each partial tile.
// ---------------------------------------------------------------------------
#define ATTN_BUF_WORDS  (64 * 68 + 64 * 72)                 // 8960 per stage
#define ATTN_PS_OFF     (2 * ATTN_BUF_WORDS)                // 17920
#define ATTN_SMEM_BYTES ((ATTN_PS_OFF + 128 * 68) * 4)      // 106496

__global__ __launch_bounds__(256, 2) void attn_kernel() {
    extern __shared__ __align__(16) unsigned smn[];
    unsigned (*Ps)[68] = (unsigned (*)[68])(smn + ATTN_PS_OFF);    // [128][68]

    int qt = (QS_ / 128 - 1) - blockIdx.x;   // heavy-first: qt 15..0
    int h  = blockIdx.y;   // 0..15
    int b  = blockIdx.z;   // 0..1
    int tid  = threadIdx.x;
    int lane = tid & 31;
    int wid  = tid >> 5;        // 0..7
    int g    = lane >> 2;       // 0..7
    int t4   = lane & 3;        // 0..3
    int rb   = wid * 16;        // warp's row base within tile (0..112)

    unsigned sbase = (unsigned)__cvta_generic_to_shared(smn);
    const float* kvbase = &g_kv[((size_t)(b * KS_)) * (2 * NH_ * HD_) + h * HD_];

    int nkt = 2 * qt + 34;   // tiles 0 .. 2qt+33 hold >=1 valid key

    // ---- Prologue: async-copy K/V tile 0 into buf 0 (overlaps Q staging) ----
    {
        unsigned kb = sbase;
        unsigned vb = sbase + 64 * 68 * 4;
#pragma unroll
        for (int it = 0; it < 4; it++) {
            int i = tid + it * 256;        // 64 rows x 16 float4
            int r = i >> 4, c4 = i & 15;
            const float* sp = kvbase + (size_t)r * (2 * NH_ * HD_) + c4 * 4;
            cp_async16(kb + (unsigned)(r * 68 + c4 * 4) * 4u, sp);
            cp_async16(vb + (unsigned)(r * 72 + c4 * 4) * 4u, sp + NH_ * HD_);
        }
        cp_commit();
    }

    // ---- Stage Q (exp2-domain scale) into Ps, lift into register A-frags ----
    {
        float4 qreg[8];
#pragma unroll
        for (int it = 0; it < 8; it++) {
            int i = tid + it * 256;            // 128 rows x 16 float4
            int r = i >> 4, c4 = i & 15;
            qreg[it] = *(const float4*)&g_q[((size_t)(b * QS_ + qt * 128 + r)) * (NH_ * HD_)
                                            + h * HD_ + c4 * 4];
        }
#pragma unroll
        for (int it = 0; it < 8; it++) {
            int i = tid + it * 256;
            int r = i >> 4, c4 = i & 15;
            float4 v = qreg[it];
            v.x *= QSCALE_; v.y *= QSCALE_; v.z *= QSCALE_; v.w *= QSCALE_;
            *(uint4*)&Ps[r][c4 * 4] = f4_as_u4(v);
        }
    }
    __syncthreads();

    unsigned qf[8][4];
#pragma unroll
    for (int ks = 0; ks < 8; ks++) {
        qf[ks][0] = Ps[rb + g][ks * 8 + t4];
        qf[ks][1] = Ps[rb + g + 8][ks * 8 + t4];
        qf[ks][2] = Ps[rb + g][ks * 8 + t4 + 4];
        qf[ks][3] = Ps[rb + g + 8][ks * 8 + t4 + 4];
    }
    // qf reads and later P writes are both confined to this warp's 16-row
    // strip of Ps, so no extra block-level fence is needed before reuse.

    float oacc[8][4];
#pragma unroll
    for (int fn = 0; fn < 8; fn++)
#pragma unroll
        for (int v = 0; v < 4; v++) oacc[fn][v] = 0.f;
    float m_lo = -INFINITY, m_hi = -INFINITY, l_lo = 0.f, l_hi = 0.f;

    for (int kt = 0; kt < nkt; kt++) {
        cp_wait0();
        __syncthreads();

        // Issue next tile's copies into the idle buffer
        if (kt + 1 < nkt) {
            const float* tb = kvbase + (size_t)(kt + 1) * 64 * (2 * NH_ * HD_);
            unsigned kb = sbase + (unsigned)((kt + 1) & 1) * (ATTN_BUF_WORDS * 4);
            unsigned vb = kb + 64 * 68 * 4;
#pragma unroll
            for (int it = 0; it < 4; it++) {
                int i = tid + it * 256;
                int r = i >> 4, c4 = i & 15;
                const float* sp = tb + (size_t)r * (2 * NH_ * HD_) + c4 * 4;
                cp_async16(kb + (unsigned)(r * 68 + c4 * 4) * 4u, sp);
                cp_async16(vb + (unsigned)(r * 72 + c4 * 4) * 4u, sp + NH_ * HD_);
            }
            cp_commit();
        }

        const unsigned (*Ks)[68] = (const unsigned (*)[68])(smn + (kt & 1) * ATTN_BUF_WORDS);
        const unsigned (*Vs)[72] = (const unsigned (*)[72])(smn + (kt & 1) * ATTN_BUF_WORDS + 64 * 68);

        // ---- S' = (Q*log2e*scale) K^T ----
        float sf[8][4];
#pragma unroll
        for (int fn = 0; fn < 8; fn++)
#pragma unroll
            for (int v = 0; v < 4; v++) sf[fn][v] = 0.f;
#pragma unroll
        for (int ks = 0; ks < 8; ks++) {
#pragma unroll
            for (int fn = 0; fn < 8; fn++) {
                unsigned b0 = Ks[fn * 8 + g][ks * 8 + t4];
                unsigned b1 = Ks[fn * 8 + g][ks * 8 + t4 + 4];
                mma_tf32(sf[fn], qf[ks][0], qf[ks][1], qf[ks][2], qf[ks][3], b0, b1);
            }
        }

        // ---- Mask (boundary crosses the final two k-tiles) ----
        if (kt >= nkt - 2) {
#pragma unroll
            for (int fn = 0; fn < 8; fn++) {
#pragma unroll
                for (int e = 0; e < 4; e++) {
                    int row = qt * 128 + rb + g + ((e >> 1) << 3);
                    int col = kt * 64 + fn * 8 + 2 * t4 + (e & 1);
                    if (col > row + MS_) sf[fn][e] = -1e30f;
                }
            }
        }

        // ---- Online softmax in exp2 domain (fragment registers) ----
        float tmax_lo = -INFINITY, tmax_hi = -INFINITY;
#pragma unroll
        for (int fn = 0; fn < 8; fn++) {
            tmax_lo = fmaxf(tmax_lo, fmaxf(sf[fn][0], sf[fn][1]));
            tmax_hi = fmaxf(tmax_hi, fmaxf(sf[fn][2], sf[fn][3]));
        }
        tmax_lo = fmaxf(tmax_lo, __shfl_xor_sync(0xffffffffu, tmax_lo, 1));
        tmax_lo = fmaxf(tmax_lo, __shfl_xor_sync(0xffffffffu, tmax_lo, 2));
        tmax_hi = fmaxf(tmax_hi, __shfl_xor_sync(0xffffffffu, tmax_hi, 1));
        tmax_hi = fmaxf(tmax_hi, __shfl_xor_sync(0xffffffffu, tmax_hi, 2));

        float mn_lo = fmaxf(m_lo, tmax_lo);
        float mn_hi = fmaxf(m_hi, tmax_hi);
        float al_lo = fexp2(m_lo - mn_lo);   // first tile: 2^(-inf) = 0
        float al_hi = fexp2(m_hi - mn_hi);

        float sum_lo = 0.f, sum_hi = 0.f;
#pragma unroll
        for (int fn = 0; fn < 8; fn++) {
            float p0 = fexp2(sf[fn][0] - mn_lo);
            float p1 = fexp2(sf[fn][1] - mn_lo);
            float p2 = fexp2(sf[fn][2] - mn_hi);
            float p3 = fexp2(sf[fn][3] - mn_hi);
            sum_lo += p0 + p1;
            sum_hi += p2 + p3;
            *(uint2*)&Ps[rb + g][fn * 8 + 2 * t4] =
                make_uint2(__float_as_uint(p0), __float_as_uint(p1));
            *(uint2*)&Ps[rb + g + 8][fn * 8 + 2 * t4] =
                make_uint2(__float_as_uint(p2), __float_as_uint(p3));
        }
        sum_lo += __shfl_xor_sync(0xffffffffu, sum_lo, 1);
        sum_lo += __shfl_xor_sync(0xffffffffu, sum_lo, 2);
        sum_hi += __shfl_xor_sync(0xffffffffu, sum_hi, 1);
        sum_hi += __shfl_xor_sync(0xffffffffu, sum_hi, 2);

        l_lo = l_lo * al_lo + sum_lo;
        l_hi = l_hi * al_hi + sum_hi;
        m_lo = mn_lo;
        m_hi = mn_hi;

#pragma unroll
        for (int fn = 0; fn < 8; fn++) {
            oacc[fn][0] *= al_lo;
            oacc[fn][1] *= al_lo;
            oacc[fn][2] *= al_hi;
            oacc[fn][3] *= al_hi;
        }
        __syncwarp();   // P written/read only within this warp's 16-row strip

        // ---- O += P V ----
#pragma unroll
        for (int ks = 0; ks < 8; ks++) {
            unsigned a0 = Ps[rb + g][ks * 8 + t4];
            unsigned a1 = Ps[rb + g + 8][ks * 8 + t4];
            unsigned a2 = Ps[rb + g][ks * 8 + t4 + 4];
            unsigned a3 = Ps[rb + g + 8][ks * 8 + t4 + 4];
#pragma unroll
            for (int fn = 0; fn < 8; fn++) {
                unsigned b0 = Vs[ks * 8 + t4][fn * 8 + g];
                unsigned b1 = Vs[ks * 8 + t4 + 4][fn * 8 + g];
                mma_tf32(oacc[fn], a0, a1, a2, a3, b0, b1);
            }
        }
    }

    // ---- Epilogue: normalize and store ----
    float inv_lo = 1.f / l_lo;
    float inv_hi = 1.f / l_hi;
    int row_lo = b * QS_ + qt * 128 + rb + g;
#pragma unroll
    for (int fn = 0; fn < 8; fn++) {
        int col = h * HD_ + fn * 8 + 2 * t4;
        *(float2*)&g_att[(size_t)row_lo * (NH_ * HD_) + col] =
            make_float2(oacc[fn][0] * inv_lo, oacc[fn][1] * inv_lo);
        *(float2*)&g_att[(size_t)(row_lo + 8) * (NH_ * HD_) + col] =
            make_float2(oacc[fn][2] * inv_hi, oacc[fn][3] * inv_hi);
    }
}

// ---------------------------------------------------------------------------
// LayerNorm over g_proj (residual already fused into the O-proj epilogue):
// out = LN(g_proj) * gamma + beta.  One block per row (H=1024).
// ---------------------------------------------------------------------------
__global__ __launch_bounds__(256) void ln_kernel(const float* __restrict__ gamma,
                                                 const float* __restrict__ beta,
                                                 float* __restrict__ out) {
    int row = blockIdx.x;
    int tid = threadIdx.x;
    size_t base = (size_t)row * H_ + tid * 4;

    float4 pv = *(const float4*)&g_proj[base];
    float y0 = pv.x, y1 = pv.y, y2 = pv.z, y3 = pv.w;

    float sum = y0 + y1 + y2 + y3;
    float sq  = y0 * y0 + y1 * y1 + y2 * y2 + y3 * y3;

    __shared__ float ssum[8], ssq[8];
#pragma unroll
    for (int o = 16; o > 0; o >>= 1) {
        sum += __shfl_xor_sync(0xffffffffu, sum, o);
        sq  += __shfl_xor_sync(0xffffffffu, sq,  o);
    }
    if ((tid & 31) == 0) { ssum[tid >> 5] = sum; ssq[tid >> 5] = sq; }
    __syncthreads();
    float ts = 0.f, tq = 0.f;
#pragma unroll
    for (int i = 0; i < 8; i++) { ts += ssum[i]; tq += ssq[i]; }

    float mu  = ts * (1.f / H_);
    float var = tq * (1.f / H_) - mu * mu;
    float inv = rsqrtf(var + LN_EPS_);

    float4 gv = *(const float4*)&gamma[tid * 4];
    float4 bv = *(const float4*)&beta[tid * 4];
    float4 o;
    o.x = (y0 - mu) * inv * gv.x + bv.x;
    o.y = (y1 - mu) * inv * gv.y + bv.y;
    o.z = (y2 - mu) * inv * gv.z + bv.z;
    o.w = (y3 - mu) * inv * gv.w + bv.w;
    *(float4*)&out[base] = o;
}

// ---------------------------------------------------------------------------
// Launcher (graph-capturable: kernel launches + non-stream attribute/query APIs)
// ---------------------------------------------------------------------------
extern "C" void kernel_launch(void* const* d_in, const int* in_sizes, int n_in,
                              void* d_out, int out_size) {
    (void)in_sizes; (void)n_in; (void)out_size;
    const float* x    = (const float*)d_in[0];
    const float* mem  = (const float*)d_in[1];
    // d_in[2] = mask — analytic (k > q + MS), computed in-kernel, not read.
    const float* W_kv = (const float*)d_in[3];
    const float* W_q  = (const float*)d_in[4];
    const float* W_o  = (const float*)d_in[5];
    const float* ln_g = (const float*)d_in[6];
    const float* ln_b = (const float*)d_in[7];
    float* out = (float*)d_out;

    cudaFuncSetAttribute(attn_kernel, cudaFuncAttributeMaxDynamicSharedMemorySize,
                         ATTN_SMEM_BYTES);
    cudaFuncSetAttribute(gemm_tf32<0, 0>, cudaFuncAttributeMaxDynamicSharedMemorySize,
                         GEMM_SMEM_BYTES);
    cudaFuncSetAttribute(gemm_tf32<1, 0>, cudaFuncAttributeMaxDynamicSharedMemorySize,
                         GEMM_SMEM_BYTES);
    cudaFuncSetAttribute(gemm_tf32<0, 1>, cudaFuncAttributeMaxDynamicSharedMemorySize,
                         GEMM_SMEM_BYTES);

    void *pkv, *pq, *patt, *pproj;
    cudaGetSymbolAddress(&pkv,   g_kv);
    cudaGetSymbolAddress(&pq,    g_q);
    cudaGetSymbolAddress(&patt,  g_att);
    cudaGetSymbolAddress(&pproj, g_proj);

    // 1. KV projection with fused concat: g_kv = concat(mem,x) @ W_kv
    gemm_tf32<1, 0><<<dim3(2048 / 128, (B_ * KS_) / 128), 256, GEMM_SMEM_BYTES>>>(
        x, mem, W_kv, nullptr, (float*)pkv, B_ * KS_, 2 * NH_ * HD_, H_);

    // 2. Q projection: g_q = x @ W_q
    gemm_tf32<0, 0><<<dim3(1024 / 128, (B_ * QS_) / 128), 256, GEMM_SMEM_BYTES>>>(
        x, nullptr, W_q, nullptr, (float*)pq, B_ * QS_, NH_ * HD_, H_);

    // 3. Tensor-core flash attention (128-query tiles, cp.async, heavy-first)
    attn_kernel<<<dim3(QS_ / 128, NH_, B_), 256, ATTN_SMEM_BYTES>>>();

    // 4. Output projection + residual: g_proj = x + g_att @ W_o
    gemm_tf32<0, 1><<<dim3(1024 / 128, (B_ * QS_) / 128), 256, GEMM_SMEM_BYTES>>>(
        (const float*)patt, nullptr, W_o, x, (float*)pproj, B_ * QS_, H_, NH_ * HD_);

    // 5. LayerNorm -> d_out
    ln_kernel<<<B_ * QS_, 256>>>(ln_g, ln_b, out);
}